// round 12
// baseline (speedup 1.0000x reference)
#include <cuda_runtime.h>
#include <cuda_bf16.h>
#include <math.h>

#define Wd 14
#define Hd 14
#define Bd 64
#define Cd 256
#define NEG 64
#define HWBC (14*14*64*256)
#define YSTR (10752*256)

#define SY (5.5f/127.0f)       // fixed Y quant scale (Y ~ N(0,1))

// Scratch (static device globals; no allocation)
__device__ __nv_bfloat16 g_ztb[HWBC];                 // [h][w][b][c] bf16 (GEMM A)
__device__ __nv_bfloat16 g_ctb[HWBC];                 // [h][w][b][c] bf16 ctx
__device__ __nv_bfloat16 g_wkb[3*Cd*Cd];              // Wk bf16
__device__ __align__(128) signed char g_Yq[3*YSTR];   // per-k Y, int8

// ---------------------------------------------------------------- init
__global__ void init_out(float* out) { if (threadIdx.x == 0) out[0] = 0.f; }

// ------------------------------------------------------------ transpose
__global__ __launch_bounds__(256) void transpose_kernel(const float* __restrict__ z,
                                                        const float* __restrict__ c) {
    __shared__ float sz[32][99];
    __shared__ float sc[32][99];
    int b  = blockIdx.x;
    int ct = blockIdx.y;
    int ht = blockIdx.z;
    const float* __restrict__ zsrc = z + ((size_t)b * Cd + ct * 32) * 196 + ht * 98;
    const float* __restrict__ csrc = c + ((size_t)b * Cd + ct * 32) * 196 + ht * 98;

    for (int i = threadIdx.x; i < 32 * 98; i += 256) {
        int row = i / 98, col = i - row * 98;
        sz[row][col] = zsrc[(size_t)row * 196 + col];
        sc[row][col] = csrc[(size_t)row * 196 + col];
    }
    __syncthreads();
    for (int i = threadIdx.x; i < 32 * 98; i += 256) {
        int hw = i >> 5, cl = i & 31;
        size_t d = (size_t)(ht * 98 + hw) * (Bd * Cd) + (size_t)b * Cd + ct * 32 + cl;
        g_ztb[d] = __float2bfloat16(sz[cl][hw]);
        g_ctb[d] = __float2bfloat16(sc[cl][hw]);
    }
}

__global__ void cvt_wk(const float* __restrict__ Wk) {
    int i = blockIdx.x * blockDim.x + threadIdx.x;
    if (i < 3 * Cd * Cd) g_wkb[i] = __float2bfloat16(Wk[i]);
}

// ---------------------------------------------------------------- GEMM (bf16 tensor core)
// Per-k launch. 128x128x32 tile, 8 warps of 64x32, 3-stage cp.async,
// one barrier per iter, int8 epilogue (Yq = round(acc/SY)).
#define SASTR 40
#define STAGE (128 * SASTR)

__device__ __forceinline__ void ldsm_x4(unsigned a, unsigned& r0, unsigned& r1,
                                        unsigned& r2, unsigned& r3) {
    asm volatile("ldmatrix.sync.aligned.m8n8.x4.shared.b16 {%0,%1,%2,%3}, [%4];"
                 : "=r"(r0), "=r"(r1), "=r"(r2), "=r"(r3) : "r"(a));
}
__device__ __forceinline__ void mma16816(float* d, const unsigned* a, const unsigned* b) {
    asm volatile("mma.sync.aligned.m16n8k16.row.col.f32.bf16.bf16.f32 "
                 "{%0,%1,%2,%3},{%4,%5,%6,%7},{%8,%9},{%0,%1,%2,%3};"
                 : "+f"(d[0]), "+f"(d[1]), "+f"(d[2]), "+f"(d[3])
                 : "r"(a[0]), "r"(a[1]), "r"(a[2]), "r"(a[3]),
                   "r"(b[0]), "r"(b[1]));
}
__device__ __forceinline__ void cp16(void* dst, const void* src) {
    unsigned d = (unsigned)__cvta_generic_to_shared(dst);
    asm volatile("cp.async.cg.shared.global [%0], [%1], 16;" :: "r"(d), "l"(src));
}
__device__ __forceinline__ int q8(float x) {
    int v = __float2int_rn(x * (127.0f / 5.5f));
    return max(-127, min(127, v));
}

__global__ __launch_bounds__(256, 2) void gemm_kernel(int k) {
    extern __shared__ __align__(16) char dynsm[];
    __nv_bfloat16* sA = (__nv_bfloat16*)dynsm;           // 3 stages
    __nv_bfloat16* sB = sA + 3 * STAGE;

    int row0 = blockIdx.x * 128;
    int o0 = blockIdx.y * 128;

    const __nv_bfloat16* __restrict__ A  = g_ztb + (size_t)(k + 2) * 896 * Cd;
    const __nv_bfloat16* __restrict__ Bw = g_wkb + (size_t)k * Cd * Cd;

    int tid = threadIdx.x;
    int warp = tid >> 5, lane = tid & 31;
    int wm = warp >> 2, wn = warp & 3;
    int lrow = tid >> 2, lcol = (tid & 3) * 8;

    const __nv_bfloat16* Ag0 = A  + (size_t)(row0 + lrow) * Cd + lcol;
    const __nv_bfloat16* Ag1 = A  + (size_t)(row0 + lrow + 64) * Cd + lcol;
    const __nv_bfloat16* Bg0 = Bw + (size_t)(o0 + lrow) * Cd + lcol;
    const __nv_bfloat16* Bg1 = Bw + (size_t)(o0 + lrow + 64) * Cd + lcol;
    int soff = lrow * SASTR + lcol;
    int soff1 = (lrow + 64) * SASTR + lcol;

    // prologue: stages 0,1
#pragma unroll
    for (int st = 0; st < 2; st++) {
        int kc = st * 32;
        cp16(sA + st * STAGE + soff,  Ag0 + kc);
        cp16(sA + st * STAGE + soff1, Ag1 + kc);
        cp16(sB + st * STAGE + soff,  Bg0 + kc);
        cp16(sB + st * STAGE + soff1, Bg1 + kc);
        asm volatile("cp.async.commit_group;");
    }

    float acc[4][4][4] = {};

#pragma unroll 1
    for (int it = 0; it < 8; it++) {
        if (it < 7) asm volatile("cp.async.wait_group 1;");
        else        asm volatile("cp.async.wait_group 0;");
        __syncthreads();
        if (it + 2 < 8) {
            int st = (it + 2) % 3;
            int kc = (it + 2) * 32;
            cp16(sA + st * STAGE + soff,  Ag0 + kc);
            cp16(sA + st * STAGE + soff1, Ag1 + kc);
            cp16(sB + st * STAGE + soff,  Bg0 + kc);
            cp16(sB + st * STAGE + soff1, Bg1 + kc);
            asm volatile("cp.async.commit_group;");
        }
        __nv_bfloat16* cA = sA + (it % 3) * STAGE;
        __nv_bfloat16* cB = sB + (it % 3) * STAGE;
#pragma unroll
        for (int kk = 0; kk < 2; kk++) {
            unsigned afr[4][4], bfr[4][2];
#pragma unroll
            for (int mt = 0; mt < 4; mt++) {
                unsigned a = (unsigned)__cvta_generic_to_shared(
                    cA + (wm * 64 + mt * 16 + (lane & 15)) * SASTR
                       + kk * 16 + (lane >> 4) * 8);
                ldsm_x4(a, afr[mt][0], afr[mt][1], afr[mt][2], afr[mt][3]);
            }
#pragma unroll
            for (int np = 0; np < 2; np++) {
                unsigned r0, r1, r2, r3;
                unsigned a = (unsigned)__cvta_generic_to_shared(
                    cB + (wn * 32 + np * 16 + (lane & 15)) * SASTR
                       + kk * 16 + (lane >> 4) * 8);
                ldsm_x4(a, r0, r1, r2, r3);
                bfr[np * 2][0] = r0; bfr[np * 2][1] = r2;
                bfr[np * 2 + 1][0] = r1; bfr[np * 2 + 1][1] = r3;
            }
#pragma unroll
            for (int mt = 0; mt < 4; mt++)
#pragma unroll
                for (int nt = 0; nt < 4; nt++)
                    mma16816(acc[mt][nt], afr[mt], bfr[nt]);
        }
    }

    // ---- int8 epilogue: stage to smem (stride 144), copy out 16B-wide
    __syncthreads();
    char* sq = dynsm;
#pragma unroll
    for (int mt = 0; mt < 4; mt++)
#pragma unroll
        for (int nt = 0; nt < 4; nt++) {
            int rl = wm * 64 + mt * 16 + (lane >> 2);
            int cl = wn * 32 + nt * 8 + (lane & 3) * 2;
            sq[rl * 144 + cl]           = (char)q8(acc[mt][nt][0]);
            sq[rl * 144 + cl + 1]       = (char)q8(acc[mt][nt][1]);
            sq[(rl + 8) * 144 + cl]     = (char)q8(acc[mt][nt][2]);
            sq[(rl + 8) * 144 + cl + 1] = (char)q8(acc[mt][nt][3]);
        }
    __syncthreads();
    signed char* Yq = g_Yq + (size_t)k * YSTR;
#pragma unroll
    for (int i = tid; i < 1024; i += 256) {
        int row = i >> 3, off = (i & 7) * 16;
        uint4 v = *(uint4*)(sq + row * 144 + off);
        *(uint4*)(Yq + (size_t)(row0 + row) * 256 + o0 + off) = v;
    }
}

// ------------------------------------------------------- dot + softmax
// Per-k launch. One warp per row. int8 Y gathers (256B/row), bf16 ctx
// quantized per-row to int8 in-kernel, dp4a dots, exact int32 accumulation.
__global__ __launch_bounds__(256, 4) void dot_kernel(const int* __restrict__ negidx,
                                                     int k, int rows,
                                                     float* __restrict__ out) {
    __shared__ int   s_part[8][16 * 33];
    __shared__ int   s_tgt[8][64];
    __shared__ float s_logit[8][68];
    __shared__ float s_loss[8];

    int warp = threadIdx.x >> 5;
    int lane = threadIdx.x & 31;
    const signed char* __restrict__ Yb = g_Yq + (size_t)k * YSTR;
    float invw = 1.0f / (3.0f * (float)rows);
    int r = blockIdx.x * 8 + warp;

    // ---- load bf16 ctx (8 values/lane), per-row int8 quantization
    uint4 cu = ((const uint4*)(g_ctb + (size_t)r * Cd))[lane];
    float2 p0 = __bfloat1622float2(*(__nv_bfloat162*)&cu.x);
    float2 p1 = __bfloat1622float2(*(__nv_bfloat162*)&cu.y);
    float2 p2 = __bfloat1622float2(*(__nv_bfloat162*)&cu.z);
    float2 p3 = __bfloat1622float2(*(__nv_bfloat162*)&cu.w);
    float m8 = fmaxf(fmaxf(fmaxf(fabsf(p0.x), fabsf(p0.y)),
                           fmaxf(fabsf(p1.x), fabsf(p1.y))),
                     fmaxf(fmaxf(fabsf(p2.x), fabsf(p2.y)),
                           fmaxf(fabsf(p3.x), fabsf(p3.y))));
#pragma unroll
    for (int o = 16; o; o >>= 1) m8 = fmaxf(m8, __shfl_xor_sync(0xffffffffu, m8, o));
    m8 = fmaxf(m8, 1e-20f);
    float inv = 127.0f / m8;
    int a0 = __float2int_rn(p0.x * inv), a1 = __float2int_rn(p0.y * inv);
    int a2 = __float2int_rn(p1.x * inv), a3 = __float2int_rn(p1.y * inv);
    int a4 = __float2int_rn(p2.x * inv), a5 = __float2int_rn(p2.y * inv);
    int a6 = __float2int_rn(p3.x * inv), a7 = __float2int_rn(p3.y * inv);
    int q0 = (a0 & 255) | ((a1 & 255) << 8) | ((a2 & 255) << 16) | (a3 << 24);
    int q1 = (a4 & 255) | ((a5 & 255) << 8) | ((a6 & 255) << 16) | (a7 << 24);
    float fscale = SY * m8 * (1.0f / 127.0f);

    // ---- main logit
    uint2 vs = *(const uint2*)(Yb + (size_t)r * 256 + lane * 8);
    int dm = __dp4a((int)vs.x, q0, __dp4a((int)vs.y, q1, 0));
#pragma unroll
    for (int o = 16; o; o >>= 1) dm += __shfl_xor_sync(0xffffffffu, dm, o);
    if (lane == 0) s_logit[warp][0] = (float)dm * fscale;

    s_tgt[warp][lane]      = negidx[(size_t)r * NEG + lane];
    s_tgt[warp][lane + 32] = negidx[(size_t)r * NEG + 32 + lane];
    __syncwarp();

    int t16  = lane & 15;
    int half = lane >> 4;

#pragma unroll 1
    for (int g = 0; g < 4; g++) {
        uint2 v[16];
#pragma unroll
        for (int i = 0; i < 16; i++) {
            int j = s_tgt[warp][g * 16 + i];
            v[i] = *(const uint2*)(Yb + (size_t)j * 256 + lane * 8);
        }
#pragma unroll
        for (int i = 0; i < 16; i++)
            s_part[warp][i * 33 + lane] =
                __dp4a((int)v[i].x, q0, __dp4a((int)v[i].y, q1, 0));
        __syncwarp();
        int s = 0;
#pragma unroll
        for (int i = 0; i < 16; i++)
            s += s_part[warp][t16 * 33 + half * 16 + i];
        s += __shfl_xor_sync(0xffffffffu, s, 16);
        if (lane < 16) s_logit[warp][1 + g * 16 + t16] = (float)s * fscale;
        __syncwarp();
    }

    // ---- softmax over 65 logits
    float v0 = s_logit[warp][lane];
    float v1 = s_logit[warp][lane + 32];
    float v2 = (lane == 0) ? s_logit[warp][64] : -INFINITY;
    float m = fmaxf(v0, fmaxf(v1, v2));
#pragma unroll
    for (int o = 16; o; o >>= 1) m = fmaxf(m, __shfl_xor_sync(0xffffffffu, m, o));
    float s = expf(v0 - m) + expf(v1 - m) + expf(v2 - m);
#pragma unroll
    for (int o = 16; o; o >>= 1) s += __shfl_xor_sync(0xffffffffu, s, o);

    if (lane == 0) {
        float l0 = s_logit[warp][0];
        float pp = expf(l0 - m) / s;
        s_loss[warp] = -logf(pp + 1e-11f) * invw;
    }
    __syncthreads();
    if (threadIdx.x < 8) {
        float x = s_loss[threadIdx.x];
        x += __shfl_xor_sync(0xffu, x, 1);
        x += __shfl_xor_sync(0xffu, x, 2);
        x += __shfl_xor_sync(0xffu, x, 4);
        if (threadIdx.x == 0) atomicAdd(out, x);
    }
}

// ---------------------------------------------------------------- host
extern "C" void kernel_launch(void* const* d_in, const int* in_sizes, int n_in,
                              void* d_out, int out_size) {
    const float* z  = (const float*)d_in[0];
    const float* c  = (const float*)d_in[1];
    const float* Wk = (const float*)d_in[2];
    const int* negs[3] = {(const int*)d_in[3], (const int*)d_in[4],
                          (const int*)d_in[5]};
    float* out = (float*)d_out;

    static int inited = 0;
    static cudaStream_t sg;
    static cudaEvent_t evR, evG[3];
    if (!inited) {
        cudaFuncSetAttribute(gemm_kernel,
                             cudaFuncAttributeMaxDynamicSharedMemorySize, 61440);
        cudaStreamCreateWithFlags(&sg, cudaStreamNonBlocking);
        cudaEventCreateWithFlags(&evR, cudaEventDisableTiming);
        for (int k = 0; k < 3; k++)
            cudaEventCreateWithFlags(&evG[k], cudaEventDisableTiming);
        inited = 1;
    }

    init_out<<<1, 32>>>(out);
    dim3 tgrid(64, 8, 2);
    transpose_kernel<<<tgrid, 256>>>(z, c);
    cvt_wk<<<(3 * Cd * Cd + 255) / 256, 256>>>(Wk);

    // fork: GEMMs on sg, dots on the main (capture) stream, overlapped per k
    cudaEventRecord(evR, 0);
    cudaStreamWaitEvent(sg, evR, 0);
    for (int k = 0; k < 3; k++) {
        int rows = (12 - k) * 896;
        dim3 ggrid(rows / 128, 2);
        gemm_kernel<<<ggrid, 256, 61440, sg>>>(k);
        cudaEventRecord(evG[k], sg);
    }
    for (int k = 0; k < 3; k++) {
        int rows = (12 - k) * 896;
        cudaStreamWaitEvent(0, evG[k], 0);
        dot_kernel<<<rows / 8, 256>>>(negs[k], k, rows, out);
    }
}

// round 13
// speedup vs baseline: 1.0769x; 1.0769x over previous
#include <cuda_runtime.h>
#include <cuda_bf16.h>
#include <math.h>

#define Wd 14
#define Hd 14
#define Bd 64
#define Cd 256
#define NEG 64
#define HWBC (14*14*64*256)
#define YSTR (10752*256)
#define ROWS0 10752
#define ROWS1 9856
#define ROWS2 8960

#define SY (5.5f/127.0f)       // fixed Y quant scale (Y ~ N(0,1))

// Scratch (static device globals; no allocation)
__device__ __nv_bfloat16 g_ztb[HWBC];                 // [h][w][b][c] bf16 (GEMM A)
__device__ __nv_bfloat16 g_ctb[HWBC];                 // [h][w][b][c] bf16 ctx
__device__ __nv_bfloat16 g_wkb[3*Cd*Cd];              // Wk bf16
__device__ __align__(128) signed char g_Yq[3*YSTR];   // per-k Y, int8

// ------------------------------------------------------------ transpose
__global__ __launch_bounds__(256) void transpose_kernel(const float* __restrict__ z,
                                                        const float* __restrict__ c) {
    __shared__ float sz[32][99];
    __shared__ float sc[32][99];
    int b  = blockIdx.x;
    int ct = blockIdx.y;
    int ht = blockIdx.z;
    const float* __restrict__ zsrc = z + ((size_t)b * Cd + ct * 32) * 196 + ht * 98;
    const float* __restrict__ csrc = c + ((size_t)b * Cd + ct * 32) * 196 + ht * 98;

    for (int i = threadIdx.x; i < 32 * 98; i += 256) {
        int row = i / 98, col = i - row * 98;
        sz[row][col] = zsrc[(size_t)row * 196 + col];
        sc[row][col] = csrc[(size_t)row * 196 + col];
    }
    __syncthreads();
    for (int i = threadIdx.x; i < 32 * 98; i += 256) {
        int hw = i >> 5, cl = i & 31;
        size_t d = (size_t)(ht * 98 + hw) * (Bd * Cd) + (size_t)b * Cd + ct * 32 + cl;
        g_ztb[d] = __float2bfloat16(sz[cl][hw]);
        g_ctb[d] = __float2bfloat16(sc[cl][hw]);
    }
}

// cvt_wk also zero-inits the output scalar (runs before any dot atomic)
__global__ void cvt_wk(const float* __restrict__ Wk, float* __restrict__ out) {
    int i = blockIdx.x * blockDim.x + threadIdx.x;
    if (i == 0) out[0] = 0.f;
    if (i < 3 * Cd * Cd) g_wkb[i] = __float2bfloat16(Wk[i]);
}

// ---------------------------------------------------------------- GEMM (bf16 tensor core)
// 128x128x32 tile, 8 warps of 64x32, 3-stage cp.async, ONE barrier per iter,
// int8 epilogue (Yq = round(acc/SY)). All three k in one grid.
#define SASTR 40
#define STAGE (128 * SASTR)

__device__ __forceinline__ void ldsm_x4(unsigned a, unsigned& r0, unsigned& r1,
                                        unsigned& r2, unsigned& r3) {
    asm volatile("ldmatrix.sync.aligned.m8n8.x4.shared.b16 {%0,%1,%2,%3}, [%4];"
                 : "=r"(r0), "=r"(r1), "=r"(r2), "=r"(r3) : "r"(a));
}
__device__ __forceinline__ void mma16816(float* d, const unsigned* a, const unsigned* b) {
    asm volatile("mma.sync.aligned.m16n8k16.row.col.f32.bf16.bf16.f32 "
                 "{%0,%1,%2,%3},{%4,%5,%6,%7},{%8,%9},{%0,%1,%2,%3};"
                 : "+f"(d[0]), "+f"(d[1]), "+f"(d[2]), "+f"(d[3])
                 : "r"(a[0]), "r"(a[1]), "r"(a[2]), "r"(a[3]),
                   "r"(b[0]), "r"(b[1]));
}
__device__ __forceinline__ void cp16(void* dst, const void* src) {
    unsigned d = (unsigned)__cvta_generic_to_shared(dst);
    asm volatile("cp.async.cg.shared.global [%0], [%1], 16;" :: "r"(d), "l"(src));
}
__device__ __forceinline__ int q8(float x) {
    int v = __float2int_rn(x * (127.0f / 5.5f));
    return max(-127, min(127, v));
}

__global__ __launch_bounds__(256, 2) void gemm_kernel() {
    extern __shared__ __align__(16) char dynsm[];
    __nv_bfloat16* sA = (__nv_bfloat16*)dynsm;           // 3 stages
    __nv_bfloat16* sB = sA + 3 * STAGE;

    int bx = blockIdx.x;
    int k, mt0;
    if (bx < 84)       { k = 0; mt0 = bx; }
    else if (bx < 161) { k = 1; mt0 = bx - 84; }
    else               { k = 2; mt0 = bx - 161; }
    int row0 = mt0 * 128;
    int o0 = blockIdx.y * 128;

    const __nv_bfloat16* __restrict__ A  = g_ztb + (size_t)(k + 2) * 896 * Cd;
    const __nv_bfloat16* __restrict__ Bw = g_wkb + (size_t)k * Cd * Cd;

    int tid = threadIdx.x;
    int warp = tid >> 5, lane = tid & 31;
    int wm = warp >> 2, wn = warp & 3;
    int lrow = tid >> 2, lcol = (tid & 3) * 8;

    const __nv_bfloat16* Ag0 = A  + (size_t)(row0 + lrow) * Cd + lcol;
    const __nv_bfloat16* Ag1 = A  + (size_t)(row0 + lrow + 64) * Cd + lcol;
    const __nv_bfloat16* Bg0 = Bw + (size_t)(o0 + lrow) * Cd + lcol;
    const __nv_bfloat16* Bg1 = Bw + (size_t)(o0 + lrow + 64) * Cd + lcol;
    int soff = lrow * SASTR + lcol;
    int soff1 = (lrow + 64) * SASTR + lcol;

    // prologue: stages 0,1
#pragma unroll
    for (int st = 0; st < 2; st++) {
        int kc = st * 32;
        cp16(sA + st * STAGE + soff,  Ag0 + kc);
        cp16(sA + st * STAGE + soff1, Ag1 + kc);
        cp16(sB + st * STAGE + soff,  Bg0 + kc);
        cp16(sB + st * STAGE + soff1, Bg1 + kc);
        asm volatile("cp.async.commit_group;");
    }

    float acc[4][4][4] = {};

#pragma unroll 1
    for (int it = 0; it < 8; it++) {
        if (it < 7) asm volatile("cp.async.wait_group 1;");
        else        asm volatile("cp.async.wait_group 0;");
        __syncthreads();
        if (it + 2 < 8) {
            int st = (it + 2) % 3;
            int kc = (it + 2) * 32;
            cp16(sA + st * STAGE + soff,  Ag0 + kc);
            cp16(sA + st * STAGE + soff1, Ag1 + kc);
            cp16(sB + st * STAGE + soff,  Bg0 + kc);
            cp16(sB + st * STAGE + soff1, Bg1 + kc);
            asm volatile("cp.async.commit_group;");
        }
        __nv_bfloat16* cA = sA + (it % 3) * STAGE;
        __nv_bfloat16* cB = sB + (it % 3) * STAGE;
#pragma unroll
        for (int kk = 0; kk < 2; kk++) {
            unsigned afr[4][4], bfr[4][2];
#pragma unroll
            for (int mt = 0; mt < 4; mt++) {
                unsigned a = (unsigned)__cvta_generic_to_shared(
                    cA + (wm * 64 + mt * 16 + (lane & 15)) * SASTR
                       + kk * 16 + (lane >> 4) * 8);
                ldsm_x4(a, afr[mt][0], afr[mt][1], afr[mt][2], afr[mt][3]);
            }
#pragma unroll
            for (int np = 0; np < 2; np++) {
                unsigned r0, r1, r2, r3;
                unsigned a = (unsigned)__cvta_generic_to_shared(
                    cB + (wn * 32 + np * 16 + (lane & 15)) * SASTR
                       + kk * 16 + (lane >> 4) * 8);
                ldsm_x4(a, r0, r1, r2, r3);
                bfr[np * 2][0] = r0; bfr[np * 2][1] = r2;
                bfr[np * 2 + 1][0] = r1; bfr[np * 2 + 1][1] = r3;
            }
#pragma unroll
            for (int mt = 0; mt < 4; mt++)
#pragma unroll
                for (int nt = 0; nt < 4; nt++)
                    mma16816(acc[mt][nt], afr[mt], bfr[nt]);
        }
    }

    // ---- int8 epilogue: stage to smem (stride 144), copy out 16B-wide
    __syncthreads();
    char* sq = dynsm;
#pragma unroll
    for (int mt = 0; mt < 4; mt++)
#pragma unroll
        for (int nt = 0; nt < 4; nt++) {
            int rl = wm * 64 + mt * 16 + (lane >> 2);
            int cl = wn * 32 + nt * 8 + (lane & 3) * 2;
            sq[rl * 144 + cl]           = (char)q8(acc[mt][nt][0]);
            sq[rl * 144 + cl + 1]       = (char)q8(acc[mt][nt][1]);
            sq[(rl + 8) * 144 + cl]     = (char)q8(acc[mt][nt][2]);
            sq[(rl + 8) * 144 + cl + 1] = (char)q8(acc[mt][nt][3]);
        }
    __syncthreads();
    signed char* Yq = g_Yq + (size_t)k * YSTR;
#pragma unroll
    for (int i = tid; i < 1024; i += 256) {
        int row = i >> 3, off = (i & 7) * 16;
        uint4 v = *(uint4*)(sq + row * 144 + off);
        *(uint4*)(Yq + (size_t)(row0 + row) * 256 + o0 + off) = v;
    }
}

// ------------------------------------------------------- dot + softmax
// One fused launch, all three k. One warp per row. int8 Y gathers (256B/row),
// bf16 ctx quantized per-row to int8 in-kernel, dp4a dots, exact int32 accum.
__global__ __launch_bounds__(256, 4) void dot_kernel(const int* __restrict__ n1,
                                                     const int* __restrict__ n2,
                                                     const int* __restrict__ n3,
                                                     float* __restrict__ out) {
    __shared__ int   s_part[8][16 * 33];
    __shared__ int   s_tgt[8][64];
    __shared__ float s_logit[8][68];
    __shared__ float s_loss[8];

    int warp = threadIdx.x >> 5;
    int lane = threadIdx.x & 31;
    int blk = blockIdx.x;

    int rblk, rows;
    const int* __restrict__ negidx;
    const signed char* __restrict__ Yb;
    if (blk < ROWS0 / 8) {
        rblk = blk; rows = ROWS0; negidx = n1; Yb = g_Yq;
    } else if (blk < ROWS0 / 8 + ROWS1 / 8) {
        rblk = blk - ROWS0 / 8; rows = ROWS1; negidx = n2; Yb = g_Yq + YSTR;
    } else {
        rblk = blk - ROWS0 / 8 - ROWS1 / 8; rows = ROWS2; negidx = n3;
        Yb = g_Yq + 2 * (size_t)YSTR;
    }
    float invw = 1.0f / (3.0f * (float)rows);
    int r = rblk * 8 + warp;

    // ---- load bf16 ctx (8 values/lane), per-row int8 quantization
    uint4 cu = ((const uint4*)(g_ctb + (size_t)r * Cd))[lane];
    float2 p0 = __bfloat1622float2(*(__nv_bfloat162*)&cu.x);
    float2 p1 = __bfloat1622float2(*(__nv_bfloat162*)&cu.y);
    float2 p2 = __bfloat1622float2(*(__nv_bfloat162*)&cu.z);
    float2 p3 = __bfloat1622float2(*(__nv_bfloat162*)&cu.w);
    float m8 = fmaxf(fmaxf(fmaxf(fabsf(p0.x), fabsf(p0.y)),
                           fmaxf(fabsf(p1.x), fabsf(p1.y))),
                     fmaxf(fmaxf(fabsf(p2.x), fabsf(p2.y)),
                           fmaxf(fabsf(p3.x), fabsf(p3.y))));
#pragma unroll
    for (int o = 16; o; o >>= 1) m8 = fmaxf(m8, __shfl_xor_sync(0xffffffffu, m8, o));
    m8 = fmaxf(m8, 1e-20f);
    float inv = 127.0f / m8;
    int a0 = __float2int_rn(p0.x * inv), a1 = __float2int_rn(p0.y * inv);
    int a2 = __float2int_rn(p1.x * inv), a3 = __float2int_rn(p1.y * inv);
    int a4 = __float2int_rn(p2.x * inv), a5 = __float2int_rn(p2.y * inv);
    int a6 = __float2int_rn(p3.x * inv), a7 = __float2int_rn(p3.y * inv);
    int q0 = (a0 & 255) | ((a1 & 255) << 8) | ((a2 & 255) << 16) | (a3 << 24);
    int q1 = (a4 & 255) | ((a5 & 255) << 8) | ((a6 & 255) << 16) | (a7 << 24);
    float fscale = SY * m8 * (1.0f / 127.0f);

    // ---- main logit
    uint2 vs = *(const uint2*)(Yb + (size_t)r * 256 + lane * 8);
    int dm = __dp4a((int)vs.x, q0, __dp4a((int)vs.y, q1, 0));
#pragma unroll
    for (int o = 16; o; o >>= 1) dm += __shfl_xor_sync(0xffffffffu, dm, o);
    if (lane == 0) s_logit[warp][0] = (float)dm * fscale;

    s_tgt[warp][lane]      = negidx[(size_t)r * NEG + lane];
    s_tgt[warp][lane + 32] = negidx[(size_t)r * NEG + 32 + lane];
    __syncwarp();

    int t16  = lane & 15;
    int half = lane >> 4;

#pragma unroll 1
    for (int g = 0; g < 4; g++) {
        uint2 v[16];
#pragma unroll
        for (int i = 0; i < 16; i++) {
            int j = s_tgt[warp][g * 16 + i];
            v[i] = *(const uint2*)(Yb + (size_t)j * 256 + lane * 8);
        }
#pragma unroll
        for (int i = 0; i < 16; i++)
            s_part[warp][i * 33 + lane] =
                __dp4a((int)v[i].x, q0, __dp4a((int)v[i].y, q1, 0));
        __syncwarp();
        int s = 0;
#pragma unroll
        for (int i = 0; i < 16; i++)
            s += s_part[warp][t16 * 33 + half * 16 + i];
        s += __shfl_xor_sync(0xffffffffu, s, 16);
        if (lane < 16) s_logit[warp][1 + g * 16 + t16] = (float)s * fscale;
        __syncwarp();
    }

    // ---- softmax over 65 logits
    float v0 = s_logit[warp][lane];
    float v1 = s_logit[warp][lane + 32];
    float v2 = (lane == 0) ? s_logit[warp][64] : -INFINITY;
    float m = fmaxf(v0, fmaxf(v1, v2));
#pragma unroll
    for (int o = 16; o; o >>= 1) m = fmaxf(m, __shfl_xor_sync(0xffffffffu, m, o));
    float s = expf(v0 - m) + expf(v1 - m) + expf(v2 - m);
#pragma unroll
    for (int o = 16; o; o >>= 1) s += __shfl_xor_sync(0xffffffffu, s, o);

    if (lane == 0) {
        float l0 = s_logit[warp][0];
        float pp = expf(l0 - m) / s;
        s_loss[warp] = -logf(pp + 1e-11f) * invw;
    }
    __syncthreads();
    if (threadIdx.x < 8) {
        float x = s_loss[threadIdx.x];
        x += __shfl_xor_sync(0xffu, x, 1);
        x += __shfl_xor_sync(0xffu, x, 2);
        x += __shfl_xor_sync(0xffu, x, 4);
        if (threadIdx.x == 0) atomicAdd(out, x);
    }
}

// ---------------------------------------------------------------- host
extern "C" void kernel_launch(void* const* d_in, const int* in_sizes, int n_in,
                              void* d_out, int out_size) {
    const float* z  = (const float*)d_in[0];
    const float* c  = (const float*)d_in[1];
    const float* Wk = (const float*)d_in[2];
    const int* n1 = (const int*)d_in[3];
    const int* n2 = (const int*)d_in[4];
    const int* n3 = (const int*)d_in[5];
    float* out = (float*)d_out;

    static int smem_set = 0;
    if (!smem_set) {
        cudaFuncSetAttribute(gemm_kernel,
                             cudaFuncAttributeMaxDynamicSharedMemorySize, 61440);
        smem_set = 1;
    }

    dim3 tgrid(64, 8, 2);
    transpose_kernel<<<tgrid, 256>>>(z, c);
    cvt_wk<<<(3 * Cd * Cd + 255) / 256, 256>>>(Wk, out);

    dim3 ggrid(231, 2);
    gemm_kernel<<<ggrid, 256, 61440>>>();

    int nblocks = ROWS0 / 8 + ROWS1 / 8 + ROWS2 / 8;
    dot_kernel<<<nblocks, 256>>>(n1, n2, n3, out);
}

// round 14
// speedup vs baseline: 1.2111x; 1.1246x over previous
#include <cuda_runtime.h>
#include <cuda_bf16.h>
#include <math.h>

#define Wd 14
#define Hd 14
#define Bd 64
#define Cd 256
#define NEG 64
#define HWBC (14*14*64*256)
#define YSTR (10752*256)
#define ROWS0 10752
#define ROWS1 9856
#define ROWS2 8960

#define SY (5.5f/127.0f)       // fixed Y quant scale (Y ~ N(0,1))

// Scratch (static device globals; no allocation)
__device__ __nv_bfloat16 g_ztb[HWBC];                 // [h][w][b][c] bf16 (GEMM A)
__device__ __nv_bfloat16 g_ctb[HWBC];                 // [h][w][b][c] bf16 ctx
__device__ __nv_bfloat16 g_wkb[3*Cd*Cd];              // Wk bf16
__device__ __align__(128) signed char g_Yq[3*YSTR];   // per-k Y, int8

// ------------------------------------------------------------ transpose
__global__ __launch_bounds__(256) void transpose_kernel(const float* __restrict__ z,
                                                        const float* __restrict__ c) {
    __shared__ float sz[32][99];
    __shared__ float sc[32][99];
    int b  = blockIdx.x;
    int ct = blockIdx.y;
    int ht = blockIdx.z;
    const float* __restrict__ zsrc = z + ((size_t)b * Cd + ct * 32) * 196 + ht * 98;
    const float* __restrict__ csrc = c + ((size_t)b * Cd + ct * 32) * 196 + ht * 98;

    for (int i = threadIdx.x; i < 32 * 98; i += 256) {
        int row = i / 98, col = i - row * 98;
        sz[row][col] = zsrc[(size_t)row * 196 + col];
        sc[row][col] = csrc[(size_t)row * 196 + col];
    }
    __syncthreads();
    for (int i = threadIdx.x; i < 32 * 98; i += 256) {
        int hw = i >> 5, cl = i & 31;
        size_t d = (size_t)(ht * 98 + hw) * (Bd * Cd) + (size_t)b * Cd + ct * 32 + cl;
        g_ztb[d] = __float2bfloat16(sz[cl][hw]);
        g_ctb[d] = __float2bfloat16(sc[cl][hw]);
    }
}

// cvt_wk also zero-inits the output scalar (runs before any dot atomic)
__global__ void cvt_wk(const float* __restrict__ Wk, float* __restrict__ out) {
    int i = blockIdx.x * blockDim.x + threadIdx.x;
    if (i == 0) out[0] = 0.f;
    if (i < 3 * Cd * Cd) g_wkb[i] = __float2bfloat16(Wk[i]);
}

// ---------------------------------------------------------------- GEMM (bf16 tensor core)
// 128x128x32 tile, 8 warps of 64x32, 3-stage cp.async, ONE barrier per iter,
// int8 epilogue (Yq = round(acc/SY)). All three k in one grid.
#define SASTR 40
#define STAGE (128 * SASTR)

__device__ __forceinline__ void ldsm_x4(unsigned a, unsigned& r0, unsigned& r1,
                                        unsigned& r2, unsigned& r3) {
    asm volatile("ldmatrix.sync.aligned.m8n8.x4.shared.b16 {%0,%1,%2,%3}, [%4];"
                 : "=r"(r0), "=r"(r1), "=r"(r2), "=r"(r3) : "r"(a));
}
__device__ __forceinline__ void mma16816(float* d, const unsigned* a, const unsigned* b) {
    asm volatile("mma.sync.aligned.m16n8k16.row.col.f32.bf16.bf16.f32 "
                 "{%0,%1,%2,%3},{%4,%5,%6,%7},{%8,%9},{%0,%1,%2,%3};"
                 : "+f"(d[0]), "+f"(d[1]), "+f"(d[2]), "+f"(d[3])
                 : "r"(a[0]), "r"(a[1]), "r"(a[2]), "r"(a[3]),
                   "r"(b[0]), "r"(b[1]));
}
__device__ __forceinline__ void cp16(void* dst, const void* src) {
    unsigned d = (unsigned)__cvta_generic_to_shared(dst);
    asm volatile("cp.async.cg.shared.global [%0], [%1], 16;" :: "r"(d), "l"(src));
}
__device__ __forceinline__ int q8(float x) {
    int v = __float2int_rn(x * (127.0f / 5.5f));
    return max(-127, min(127, v));
}

__global__ __launch_bounds__(256, 2) void gemm_kernel() {
    extern __shared__ __align__(16) char dynsm[];
    __nv_bfloat16* sA = (__nv_bfloat16*)dynsm;           // 3 stages
    __nv_bfloat16* sB = sA + 3 * STAGE;

    int bx = blockIdx.x;
    int k, mt0;
    if (bx < 84)       { k = 0; mt0 = bx; }
    else if (bx < 161) { k = 1; mt0 = bx - 84; }
    else               { k = 2; mt0 = bx - 161; }
    int row0 = mt0 * 128;
    int o0 = blockIdx.y * 128;

    const __nv_bfloat16* __restrict__ A  = g_ztb + (size_t)(k + 2) * 896 * Cd;
    const __nv_bfloat16* __restrict__ Bw = g_wkb + (size_t)k * Cd * Cd;

    int tid = threadIdx.x;
    int warp = tid >> 5, lane = tid & 31;
    int wm = warp >> 2, wn = warp & 3;
    int lrow = tid >> 2, lcol = (tid & 3) * 8;

    const __nv_bfloat16* Ag0 = A  + (size_t)(row0 + lrow) * Cd + lcol;
    const __nv_bfloat16* Ag1 = A  + (size_t)(row0 + lrow + 64) * Cd + lcol;
    const __nv_bfloat16* Bg0 = Bw + (size_t)(o0 + lrow) * Cd + lcol;
    const __nv_bfloat16* Bg1 = Bw + (size_t)(o0 + lrow + 64) * Cd + lcol;
    int soff = lrow * SASTR + lcol;
    int soff1 = (lrow + 64) * SASTR + lcol;

    // prologue: stages 0,1
#pragma unroll
    for (int st = 0; st < 2; st++) {
        int kc = st * 32;
        cp16(sA + st * STAGE + soff,  Ag0 + kc);
        cp16(sA + st * STAGE + soff1, Ag1 + kc);
        cp16(sB + st * STAGE + soff,  Bg0 + kc);
        cp16(sB + st * STAGE + soff1, Bg1 + kc);
        asm volatile("cp.async.commit_group;");
    }

    float acc[4][4][4] = {};

#pragma unroll 1
    for (int it = 0; it < 8; it++) {
        if (it < 7) asm volatile("cp.async.wait_group 1;");
        else        asm volatile("cp.async.wait_group 0;");
        __syncthreads();
        if (it + 2 < 8) {
            int st = (it + 2) % 3;
            int kc = (it + 2) * 32;
            cp16(sA + st * STAGE + soff,  Ag0 + kc);
            cp16(sA + st * STAGE + soff1, Ag1 + kc);
            cp16(sB + st * STAGE + soff,  Bg0 + kc);
            cp16(sB + st * STAGE + soff1, Bg1 + kc);
            asm volatile("cp.async.commit_group;");
        }
        __nv_bfloat16* cA = sA + (it % 3) * STAGE;
        __nv_bfloat16* cB = sB + (it % 3) * STAGE;
#pragma unroll
        for (int kk = 0; kk < 2; kk++) {
            unsigned afr[4][4], bfr[4][2];
#pragma unroll
            for (int mt = 0; mt < 4; mt++) {
                unsigned a = (unsigned)__cvta_generic_to_shared(
                    cA + (wm * 64 + mt * 16 + (lane & 15)) * SASTR
                       + kk * 16 + (lane >> 4) * 8);
                ldsm_x4(a, afr[mt][0], afr[mt][1], afr[mt][2], afr[mt][3]);
            }
#pragma unroll
            for (int np = 0; np < 2; np++) {
                unsigned r0, r1, r2, r3;
                unsigned a = (unsigned)__cvta_generic_to_shared(
                    cB + (wn * 32 + np * 16 + (lane & 15)) * SASTR
                       + kk * 16 + (lane >> 4) * 8);
                ldsm_x4(a, r0, r1, r2, r3);
                bfr[np * 2][0] = r0; bfr[np * 2][1] = r2;
                bfr[np * 2 + 1][0] = r1; bfr[np * 2 + 1][1] = r3;
            }
#pragma unroll
            for (int mt = 0; mt < 4; mt++)
#pragma unroll
                for (int nt = 0; nt < 4; nt++)
                    mma16816(acc[mt][nt], afr[mt], bfr[nt]);
        }
    }

    // ---- int8 epilogue: stage to smem (stride 144), copy out 16B-wide
    __syncthreads();
    char* sq = dynsm;
#pragma unroll
    for (int mt = 0; mt < 4; mt++)
#pragma unroll
        for (int nt = 0; nt < 4; nt++) {
            int rl = wm * 64 + mt * 16 + (lane >> 2);
            int cl = wn * 32 + nt * 8 + (lane & 3) * 2;
            sq[rl * 144 + cl]           = (char)q8(acc[mt][nt][0]);
            sq[rl * 144 + cl + 1]       = (char)q8(acc[mt][nt][1]);
            sq[(rl + 8) * 144 + cl]     = (char)q8(acc[mt][nt][2]);
            sq[(rl + 8) * 144 + cl + 1] = (char)q8(acc[mt][nt][3]);
        }
    __syncthreads();
    signed char* Yq = g_Yq + (size_t)k * YSTR;
#pragma unroll
    for (int i = tid; i < 1024; i += 256) {
        int row = i >> 3, off = (i & 7) * 16;
        uint4 v = *(uint4*)(sq + row * 144 + off);
        *(uint4*)(Yq + (size_t)(row0 + row) * 256 + o0 + off) = v;
    }
}

// ------------------------------------------------------- dot + softmax
// One warp per row. 8 lanes per target (4 groups x 2 slots = 8 targets/pass),
// each lane: 2 LDG.128 of the Y row + 8-deep dp4a chain vs register ctx slice,
// 3-shuffle group reduction. No s_part smem traffic.
__global__ __launch_bounds__(256, 4) void dot_kernel(const int* __restrict__ n1,
                                                     const int* __restrict__ n2,
                                                     const int* __restrict__ n3,
                                                     float* __restrict__ out) {
    __shared__ int   s_ctx[8][64];
    __shared__ int   s_tgt[8][64];
    __shared__ float s_logit[8][68];
    __shared__ float s_loss[8];

    int warp = threadIdx.x >> 5;
    int lane = threadIdx.x & 31;
    int blk = blockIdx.x;

    int rblk, rows;
    const int* __restrict__ negidx;
    const signed char* __restrict__ Yb;
    if (blk < ROWS0 / 8) {
        rblk = blk; rows = ROWS0; negidx = n1; Yb = g_Yq;
    } else if (blk < ROWS0 / 8 + ROWS1 / 8) {
        rblk = blk - ROWS0 / 8; rows = ROWS1; negidx = n2; Yb = g_Yq + YSTR;
    } else {
        rblk = blk - ROWS0 / 8 - ROWS1 / 8; rows = ROWS2; negidx = n3;
        Yb = g_Yq + 2 * (size_t)YSTR;
    }
    float invw = 1.0f / (3.0f * (float)rows);
    int r = rblk * 8 + warp;

    // ---- load bf16 ctx (8 values/lane), per-row int8 quantization
    uint4 cu = ((const uint4*)(g_ctb + (size_t)r * Cd))[lane];
    float2 p0 = __bfloat1622float2(*(__nv_bfloat162*)&cu.x);
    float2 p1 = __bfloat1622float2(*(__nv_bfloat162*)&cu.y);
    float2 p2 = __bfloat1622float2(*(__nv_bfloat162*)&cu.z);
    float2 p3 = __bfloat1622float2(*(__nv_bfloat162*)&cu.w);
    float m8 = fmaxf(fmaxf(fmaxf(fabsf(p0.x), fabsf(p0.y)),
                           fmaxf(fabsf(p1.x), fabsf(p1.y))),
                     fmaxf(fmaxf(fabsf(p2.x), fabsf(p2.y)),
                           fmaxf(fabsf(p3.x), fabsf(p3.y))));
#pragma unroll
    for (int o = 16; o; o >>= 1) m8 = fmaxf(m8, __shfl_xor_sync(0xffffffffu, m8, o));
    m8 = fmaxf(m8, 1e-20f);
    float inv = 127.0f / m8;
    int a0 = __float2int_rn(p0.x * inv), a1 = __float2int_rn(p0.y * inv);
    int a2 = __float2int_rn(p1.x * inv), a3 = __float2int_rn(p1.y * inv);
    int a4 = __float2int_rn(p2.x * inv), a5 = __float2int_rn(p2.y * inv);
    int a6 = __float2int_rn(p3.x * inv), a7 = __float2int_rn(p3.y * inv);
    int q0 = (a0 & 255) | ((a1 & 255) << 8) | ((a2 & 255) << 16) | (a3 << 24);
    int q1 = (a4 & 255) | ((a5 & 255) << 8) | ((a6 & 255) << 16) | (a7 << 24);
    float fscale = SY * m8 * (1.0f / 127.0f);

    // ---- main logit (full-warp, old slice mapping: lane covers bytes 8*lane)
    uint2 vs = *(const uint2*)(Yb + (size_t)r * 256 + lane * 8);
    int dm = __dp4a((int)vs.x, q0, __dp4a((int)vs.y, q1, 0));
#pragma unroll
    for (int o = 16; o; o >>= 1) dm += __shfl_xor_sync(0xffffffffu, dm, o);
    if (lane == 0) s_logit[warp][0] = (float)dm * fscale;

    // ---- stash packed ctx row + target indices
    s_ctx[warp][2 * lane]     = q0;
    s_ctx[warp][2 * lane + 1] = q1;
    s_tgt[warp][lane]      = negidx[(size_t)r * NEG + lane];
    s_tgt[warp][lane + 32] = negidx[(size_t)r * NEG + 32 + lane];
    __syncwarp();

    // ---- per-lane ctx slice for the group scheme:
    // group g = lane>>3, l = lane&7. Lane covers row chunks l and l+8
    // (chunk = 16 bytes = ctx ints 4c..4c+3).
    int g = lane >> 3;
    int l = lane & 7;
    int4 ca = *(const int4*)&s_ctx[warp][4 * l];
    int4 cb = *(const int4*)&s_ctx[warp][32 + 4 * l];

#pragma unroll 1
    for (int p = 0; p < 8; p++) {
        int ja = s_tgt[warp][p * 8 + g];
        int jb = s_tgt[warp][p * 8 + 4 + g];
        const uint4* Ra = (const uint4*)(Yb + (size_t)ja * 256);
        const uint4* Rb = (const uint4*)(Yb + (size_t)jb * 256);
        uint4 va0 = Ra[l], va1 = Ra[l + 8];
        uint4 vb0 = Rb[l], vb1 = Rb[l + 8];

        int da = __dp4a((int)va0.x, ca.x, 0);
        int db = __dp4a((int)vb0.x, ca.x, 0);
        da = __dp4a((int)va0.y, ca.y, da);
        db = __dp4a((int)vb0.y, ca.y, db);
        da = __dp4a((int)va0.z, ca.z, da);
        db = __dp4a((int)vb0.z, ca.z, db);
        da = __dp4a((int)va0.w, ca.w, da);
        db = __dp4a((int)vb0.w, ca.w, db);
        da = __dp4a((int)va1.x, cb.x, da);
        db = __dp4a((int)vb1.x, cb.x, db);
        da = __dp4a((int)va1.y, cb.y, da);
        db = __dp4a((int)vb1.y, cb.y, db);
        da = __dp4a((int)va1.z, cb.z, da);
        db = __dp4a((int)vb1.z, cb.z, db);
        da = __dp4a((int)va1.w, cb.w, da);
        db = __dp4a((int)vb1.w, cb.w, db);

        da += __shfl_xor_sync(0xffffffffu, da, 1);
        db += __shfl_xor_sync(0xffffffffu, db, 1);
        da += __shfl_xor_sync(0xffffffffu, da, 2);
        db += __shfl_xor_sync(0xffffffffu, db, 2);
        da += __shfl_xor_sync(0xffffffffu, da, 4);
        db += __shfl_xor_sync(0xffffffffu, db, 4);
        if (l == 0) {
            s_logit[warp][1 + p * 8 + g]     = (float)da * fscale;
            s_logit[warp][1 + p * 8 + 4 + g] = (float)db * fscale;
        }
    }
    __syncwarp();

    // ---- softmax over 65 logits (slot 0 = main)
    float v0 = s_logit[warp][lane];
    float v1 = s_logit[warp][lane + 32];
    float v2 = (lane == 0) ? s_logit[warp][64] : -INFINITY;
    float m = fmaxf(v0, fmaxf(v1, v2));
#pragma unroll
    for (int o = 16; o; o >>= 1) m = fmaxf(m, __shfl_xor_sync(0xffffffffu, m, o));
    float s = expf(v0 - m) + expf(v1 - m) + expf(v2 - m);
#pragma unroll
    for (int o = 16; o; o >>= 1) s += __shfl_xor_sync(0xffffffffu, s, o);

    if (lane == 0) {
        float l0 = s_logit[warp][0];
        float pp = expf(l0 - m) / s;
        s_loss[warp] = -logf(pp + 1e-11f) * invw;
    }
    __syncthreads();
    if (threadIdx.x < 8) {
        float x = s_loss[threadIdx.x];
        x += __shfl_xor_sync(0xffu, x, 1);
        x += __shfl_xor_sync(0xffu, x, 2);
        x += __shfl_xor_sync(0xffu, x, 4);
        if (threadIdx.x == 0) atomicAdd(out, x);
    }
}

// ---------------------------------------------------------------- host
extern "C" void kernel_launch(void* const* d_in, const int* in_sizes, int n_in,
                              void* d_out, int out_size) {
    const float* z  = (const float*)d_in[0];
    const float* c  = (const float*)d_in[1];
    const float* Wk = (const float*)d_in[2];
    const int* n1 = (const int*)d_in[3];
    const int* n2 = (const int*)d_in[4];
    const int* n3 = (const int*)d_in[5];
    float* out = (float*)d_out;

    static int smem_set = 0;
    if (!smem_set) {
        cudaFuncSetAttribute(gemm_kernel,
                             cudaFuncAttributeMaxDynamicSharedMemorySize, 61440);
        smem_set = 1;
    }

    dim3 tgrid(64, 8, 2);
    transpose_kernel<<<tgrid, 256>>>(z, c);
    cvt_wk<<<(3 * Cd * Cd + 255) / 256, 256>>>(Wk, out);

    dim3 ggrid(231, 2);
    gemm_kernel<<<ggrid, 256, 61440>>>();

    int nblocks = ROWS0 / 8 + ROWS1 / 8 + ROWS2 / 8;
    dot_kernel<<<nblocks, 256>>>(n1, n2, n3, out);
}